// round 13
// baseline (speedup 1.0000x reference)
#include <cuda_runtime.h>
#include <cstdint>
#include <cstddef>

#define ULL unsigned long long

__device__ __forceinline__ ULL pks(float s) {
    ULL r; asm("mov.b64 %0, {%1, %1};" : "=l"(r) : "f"(s)); return r;
}
__device__ __forceinline__ ULL pk2(float lo, float hi) {
    ULL r; asm("mov.b64 %0, {%1, %2};" : "=l"(r) : "f"(lo), "f"(hi)); return r;
}
__device__ __forceinline__ void upk(ULL v, float& lo, float& hi) {
    asm("mov.b64 {%0, %1}, %2;" : "=f"(lo), "=f"(hi) : "l"(v));
}
__device__ __forceinline__ ULL f2fma(ULL a, ULL b, ULL c) {
    ULL d; asm("fma.rn.f32x2 %0, %1, %2, %3;" : "=l"(d) : "l"(a), "l"(b), "l"(c)); return d;
}
__device__ __forceinline__ ULL f2add(ULL a, ULL b) {
    ULL d; asm("add.rn.f32x2 %0, %1, %2;" : "=l"(d) : "l"(a), "l"(b)); return d;
}
// fp16x2 word -> packed f32x2 (lo -> lo)
__device__ __forceinline__ ULL h2f2(uint32_t w) {
    float lo, hi;
    asm("{\n\t.reg .f16 l, h;\n\tmov.b32 {l, h}, %2;\n\tcvt.f32.f16 %0, l;\n\tcvt.f32.f16 %1, h;\n\t}"
        : "=f"(lo), "=f"(hi) : "r"(w));
    return pk2(lo, hi);
}
// fp16x2 word -> two duplicated packed f32x2 operands
__device__ __forceinline__ void h2dup(uint32_t w, ULL& d0, ULL& d1) {
    float lo, hi;
    asm("{\n\t.reg .f16 l, h;\n\tmov.b32 {l, h}, %2;\n\tcvt.f32.f16 %0, l;\n\tcvt.f32.f16 %1, h;\n\t}"
        : "=f"(lo), "=f"(hi) : "r"(w));
    d0 = pks(lo); d1 = pks(hi);
}
__device__ __forceinline__ uint32_t f2h2(float lo, float hi) {
    uint32_t r; asm("cvt.rn.f16x2.f32 %0, %1, %2;" : "=r"(r) : "f"(hi), "f"(lo)); return r;
}
__device__ __forceinline__ float sigm(float x) { return __fdividef(1.f, 1.f + __expf(-x)); }
__device__ __forceinline__ float tanhf_(float x) {
    float ax = fabsf(x);
    float e = __expf(-2.f * ax);
    return copysignf(__fdividef(1.f - e, 1.f + e), x);
}

// ---- shared memory layout (float offsets) ----
#define OFF_W3U  0       // k-pair packed, 1024
#define OFF_W5U  1024    // 1024
#define OFF_W34A 2048    // [k][h2][w3lo,w3hi,w4lo,w4hi] 2048
#define OFF_W34B 4096    // 2048
#define OFF_W5A  6144    // k-pair packed 1024
#define OFF_W5B  7168    // 1024
#define OFF_WOT  8192    // 1024
#define OFF_WRXT 9216    // 512
#define OFF_WRYT 9728    // 512
#define OFF_WR2  10240   // 16
#define OFF_B3W  10256
#define OFF_B3U  10288
#define OFF_B4W  10320
#define OFF_B5W  10352
#define OFF_B5U  10384
#define OFF_BO   10416
#define OFF_BRX  10432
#define OFF_BRY  10448
#define OFF_BR2  10464   // 16
#define OFF_MB   10480   // mask bitset u32[48]
#define OFF_XC   10528   // precomputed x0 @ WoT_hi: 96x16 = 1536
#define OFF_NODESP 12064 // fp32 nodes 97 x 36 (row 96 = zero)
#define OFF_AP   15556   // 3456: z parking (loop) / out[96][16] (readout)
#define OFF_MP   19012   // 2100: readout scratch (rfcx 256, rfcy 1360, s 400)
#define OFF_NH16 21112   // fp16 nodes: 97 x 80B = 1940
#define OFF_AH16 23052   // fp16 a: 96 x 80B = 1920
#define OFF_MH16 24972   // fp16 m: 96 x 80B = 1920
#define OFF_HL   26892   // u16 headlist[16][80] = 640
#define OFF_TL   27532   // u16 taillist[80][16] = 640
#define OFF_HC   28172   // int[16]
#define OFF_TC   28188   // int[80]
#define SMEM_FLOATS 28268
#define SMEM_BYTES (SMEM_FLOATS * 4)   // 113,072 B -> 2 CTAs/SM

#define RS 36
#define RSU 18
#define NBROW 80   // fp16 row stride in bytes

__global__ void __launch_bounds__(256, 2)
ggnn_kernel(const float* __restrict__ xin,
            const float* __restrict__ maskg,
            const float* __restrict__ W3w, const float* __restrict__ b3w,
            const float* __restrict__ W3u, const float* __restrict__ b3u,
            const float* __restrict__ W4w, const float* __restrict__ b4w,
            const float* __restrict__ W5w, const float* __restrict__ b5w,
            const float* __restrict__ W5u, const float* __restrict__ b5u,
            const float* __restrict__ Wo,  const float* __restrict__ bo,
            const float* __restrict__ Wrx, const float* __restrict__ brx,
            const float* __restrict__ Wry, const float* __restrict__ bry,
            const float* __restrict__ Wr2, const float* __restrict__ br2,
            float* __restrict__ outp)
{
    extern __shared__ float sm[];
    const int t = threadIdx.x;
    const int b = blockIdx.x;
    char* nh16 = reinterpret_cast<char*>(sm + OFF_NH16);
    char* ah16 = reinterpret_cast<char*>(sm + OFF_AH16);
    char* mh16 = reinterpret_cast<char*>(sm + OFF_MH16);

    // ---- stage weights + biases + nodes ----
    for (int idx = t; idx < 2048; idx += 256) {
        int quad = idx >> 2, q = idx & 3;
        int k = quad >> 4, h2i = quad & 15;
        int h = 2 * h2i + (q & 1);
        const float* Wsrc = (q < 2) ? W3w : W4w;
        sm[OFF_W34A + idx] = Wsrc[h * 64 + k];
        sm[OFF_W34B + idx] = Wsrc[h * 64 + 32 + k];
    }
    for (int idx = t; idx < 1024; idx += 256) {
        int j = idx & 3, h2i = (idx >> 2) & 15, k2 = idx >> 6;
        int k = 2 * k2 + (j >> 1), h = 2 * h2i + (j & 1);
        sm[OFF_W3U + idx] = W3u[h * 32 + k];
        sm[OFF_W5U + idx] = W5u[h * 32 + k];
        sm[OFF_W5A + idx] = W5w[h * 64 + k];
        sm[OFF_W5B + idx] = W5w[h * 64 + 32 + k];
        int k2o = idx >> 4, o = idx & 15;
        sm[OFF_WOT + idx] = Wo[o * 64 + k2o];
    }
    for (int idx = t; idx < 512; idx += 256) {
        int k = idx >> 4, o = idx & 15;
        sm[OFF_WRXT + idx] = Wrx[o * 32 + k];
        sm[OFF_WRYT + idx] = Wry[o * 32 + k];
    }
    if (t < 32) {
        sm[OFF_B3W + t] = b3w[t]; sm[OFF_B3U + t] = b3u[t];
        sm[OFF_B4W + t] = b4w[t]; sm[OFF_B5W + t] = b5w[t];
        sm[OFF_B5U + t] = b5u[t];
    }
    if (t < 16) {
        sm[OFF_BO + t] = bo[t]; sm[OFF_BRX + t] = brx[t];
        sm[OFF_BRY + t] = bry[t]; sm[OFF_WR2 + t] = Wr2[t];
    }
    if (t == 0) sm[OFF_BR2] = br2[0];
    if (t < 36) sm[OFF_NODESP + 96 * RS + t] = 0.f;
    if (t < 20) reinterpret_cast<uint32_t*>(nh16 + 96 * NBROW)[t] = 0u;
    {
        const float4* xp = reinterpret_cast<const float4*>(xin + (size_t)b * 3072);
#pragma unroll
        for (int q = 0; q < 3; q++) {
            int idx = t + (q << 8);
            float4 v = xp[idx];
            int i = idx >> 3, kq = idx & 7;
            *reinterpret_cast<float4*>(sm + OFF_NODESP + i * RS + kq * 4) = v;
            uint32_t lo = f2h2(v.x, v.y), hi = f2h2(v.z, v.w);
            *reinterpret_cast<ULL*>(nh16 + i * NBROW + kq * 8) = ((ULL)hi << 32) | lo;
        }
    }
    __syncthreads();

    // ---- XC = x0 @ WoT_hi (static part of readout) + sparse lists + bitset ----
#pragma unroll 1
    for (int q = 0; q < 6; q++) {
        int item = t + (q << 8);
        int i = item >> 4, o = item & 15;
        const float* nrow = sm + OFF_NODESP + i * RS;   // == x0 now
        float acc = 0.f;
#pragma unroll
        for (int k = 0; k < 32; k++) acc = fmaf(sm[OFF_WOT + (32 + k) * 16 + o], nrow[k], acc);
        sm[OFF_XC + i * 16 + o] = acc;
    }
    uint16_t* hl16 = reinterpret_cast<uint16_t*>(sm + OFF_HL);
    uint16_t* tl16 = reinterpret_cast<uint16_t*>(sm + OFF_TL);
    int* headcnt = reinterpret_cast<int*>(sm + OFF_HC);
    int* tailcnt = reinterpret_cast<int*>(sm + OFF_TC);
    uint32_t* mbits = reinterpret_cast<uint32_t*>(sm + OFF_MB);
    if (t < 16) {
        int c = 0;
        uint32_t w0 = 0, w1 = 0, w2 = 0;
        for (int j = 0; j < 80; j++) {
            if (maskg[t * 80 + j] != 0.f) {
                hl16[t * 80 + c++] = (uint16_t)((16 + j) * NBROW);
                if (j < 32) w0 |= 1u << j;
                else if (j < 64) w1 |= 1u << (j - 32);
                else w2 |= 1u << (j - 64);
            }
        }
        if (c & 1) hl16[t * 80 + c++] = (uint16_t)(96 * NBROW);
        headcnt[t] = c;
        mbits[t * 3 + 0] = w0; mbits[t * 3 + 1] = w1; mbits[t * 3 + 2] = w2;
    } else if (t < 96) {
        int j = t - 16, c = 0;
        for (int i = 0; i < 16; i++)
            if (maskg[i * 80 + j] != 0.f) tl16[j * 16 + c++] = (uint16_t)(i * NBROW);
        if (c & 1) tl16[j * 16 + c++] = (uint16_t)(96 * NBROW);
        tailcnt[j] = c;
    }
    __syncthreads();

    const int h2 = t & 15;
    const int g  = t >> 4;
    const int it0 = 16 + g * 5;
    const int ii[6] = { g, it0, it0 + 1, it0 + 2, it0 + 3, it0 + 4 };

    ULL* nodes2p = reinterpret_cast<ULL*>(sm + OFF_NODESP);
    ULL* a2p     = reinterpret_cast<ULL*>(sm + OFF_AP);   // z parking

    // ================= T=5 recurrent iterations =================
#pragma unroll 1
    for (int step = 0; step < 5; step++) {
        // ---- Phase A: sparse message pass (fp16 in, fp16 out) ----
#pragma unroll 1
        for (int c = 0; c < 3; c++) {
            int item = t + (c << 8);
            int r = item >> 3, q = item & 7;
            int cnt;
            const uint16_t* lst;
            if (r < 16) { cnt = headcnt[r]; lst = hl16 + r * 80; }
            else        { cnt = tailcnt[r - 16]; lst = tl16 + (r - 16) * 16; }
            const char* nbq = nh16 + q * 8;
            ULL acc0 = 0, acc1 = 0;
            for (int ci = 0; ci < cnt; ci += 2) {
                uint32_t wv = *reinterpret_cast<const uint32_t*>(lst + ci);
                ULL p0 = *reinterpret_cast<const ULL*>(nbq + (wv & 0xFFFF));
                ULL p1 = *reinterpret_cast<const ULL*>(nbq + (wv >> 16));
                acc0 = f2add(acc0, h2f2((uint32_t)p0));
                acc1 = f2add(acc1, h2f2((uint32_t)(p0 >> 32)));
                acc0 = f2add(acc0, h2f2((uint32_t)p1));
                acc1 = f2add(acc1, h2f2((uint32_t)(p1 >> 32)));
            }
            float a0, a1, a2, a3;
            upk(acc0, a0, a1); upk(acc1, a2, a3);
            uint32_t lo = f2h2(a0, a1), hi = f2h2(a2, a3);
            *reinterpret_cast<ULL*>(ah16 + r * NBROW + q * 8) = ((ULL)hi << 32) | lo;
        }
        __syncthreads();

        // ---- B1a: u3 = nodes(fp16) @ W3u^T + b3u (NB=6) ----
        ULL u3r[6];
        {
            const ULL b3u2 = *reinterpret_cast<const ULL*>(sm + OFF_B3U + 2 * h2);
#pragma unroll
            for (int n = 0; n < 6; n++) u3r[n] = b3u2;
#pragma unroll
            for (int q2 = 0; q2 < 4; q2++) {
                uint4 n4[6];
#pragma unroll
                for (int n = 0; n < 6; n++)
                    n4[n] = *reinterpret_cast<const uint4*>(nh16 + ii[n] * NBROW + q2 * 16);
#pragma unroll
                for (int w = 0; w < 4; w++) {
                    int k2 = q2 * 4 + w;
                    float4 wp = *reinterpret_cast<const float4*>(sm + OFF_W3U + (k2 * 16 + h2) * 4);
                    const ULL* wu = reinterpret_cast<const ULL*>(&wp);
#pragma unroll
                    for (int n = 0; n < 6; n++) {
                        ULL d0, d1; h2dup(reinterpret_cast<const uint32_t*>(&n4[n])[w], d0, d1);
                        u3r[n] = f2fma(wu[0], d0, u3r[n]);
                        u3r[n] = f2fma(wu[1], d1, u3r[n]);
                    }
                }
            }
        }

        ULL g5r[6];
        // ---- B1b: head gates (NB=1, a-weight set) ----
        {
            ULL g3 = *reinterpret_cast<const ULL*>(sm + OFF_B3W + 2 * h2);
            ULL g4 = *reinterpret_cast<const ULL*>(sm + OFF_B4W + 2 * h2);
            ULL g5 = *reinterpret_cast<const ULL*>(sm + OFF_B5W + 2 * h2);
#pragma unroll
            for (int q2 = 0; q2 < 4; q2++) {
                uint4 a4 = *reinterpret_cast<const uint4*>(ah16 + g * NBROW + q2 * 16);
#pragma unroll
                for (int w = 0; w < 4; w++) {
                    int k2 = q2 * 4 + w;
                    float4 wf0 = *reinterpret_cast<const float4*>(sm + OFF_W34A + ((2 * k2) * 16 + h2) * 4);
                    float4 wf1 = *reinterpret_cast<const float4*>(sm + OFF_W34A + ((2 * k2 + 1) * 16 + h2) * 4);
                    float4 w5p = *reinterpret_cast<const float4*>(sm + OFF_W5A + (k2 * 16 + h2) * 4);
                    const ULL* f0 = reinterpret_cast<const ULL*>(&wf0);
                    const ULL* f1 = reinterpret_cast<const ULL*>(&wf1);
                    const ULL* w5 = reinterpret_cast<const ULL*>(&w5p);
                    ULL d0, d1; h2dup(reinterpret_cast<const uint32_t*>(&a4)[w], d0, d1);
                    g3 = f2fma(f0[0], d0, g3); g4 = f2fma(f0[1], d0, g4); g5 = f2fma(w5[0], d0, g5);
                    g3 = f2fma(f1[0], d1, g3); g4 = f2fma(f1[1], d1, g4); g5 = f2fma(w5[1], d1, g5);
                }
            }
            ULL s3 = f2add(g3, u3r[0]), s4 = f2add(g4, u3r[0]);
            float s3x, s3y, s4x, s4y, ox, oy;
            upk(s3, s3x, s3y); upk(s4, s4x, s4y);
            upk(nodes2p[g * RSU + h2], ox, oy);
            *reinterpret_cast<uint32_t*>(mh16 + g * NBROW + h2 * 4) = f2h2(sigm(s4x) * ox, sigm(s4y) * oy);
            a2p[g * RSU + h2] = pk2(sigm(s3x), sigm(s3y));   // park z
            g5r[0] = g5;
        }

        // ---- B1c: tail gates (NB=5, b-weight set) ----
        {
            ULL g3[5], g4[5];
            {
                const ULL b3w2 = *reinterpret_cast<const ULL*>(sm + OFF_B3W + 2 * h2);
                const ULL b4w2 = *reinterpret_cast<const ULL*>(sm + OFF_B4W + 2 * h2);
                const ULL b5w2 = *reinterpret_cast<const ULL*>(sm + OFF_B5W + 2 * h2);
#pragma unroll
                for (int n = 0; n < 5; n++) { g3[n] = b3w2; g4[n] = b4w2; g5r[1 + n] = b5w2; }
            }
#pragma unroll
            for (int q2 = 0; q2 < 4; q2++) {
                uint4 a4[5];
#pragma unroll
                for (int n = 0; n < 5; n++)
                    a4[n] = *reinterpret_cast<const uint4*>(ah16 + (it0 + n) * NBROW + q2 * 16);
#pragma unroll
                for (int w = 0; w < 4; w++) {
                    int k2 = q2 * 4 + w;
                    float4 wf0 = *reinterpret_cast<const float4*>(sm + OFF_W34B + ((2 * k2) * 16 + h2) * 4);
                    float4 wf1 = *reinterpret_cast<const float4*>(sm + OFF_W34B + ((2 * k2 + 1) * 16 + h2) * 4);
                    float4 w5p = *reinterpret_cast<const float4*>(sm + OFF_W5B + (k2 * 16 + h2) * 4);
                    const ULL* f0 = reinterpret_cast<const ULL*>(&wf0);
                    const ULL* f1 = reinterpret_cast<const ULL*>(&wf1);
                    const ULL* w5 = reinterpret_cast<const ULL*>(&w5p);
#pragma unroll
                    for (int n = 0; n < 5; n++) {
                        ULL d0, d1; h2dup(reinterpret_cast<const uint32_t*>(&a4[n])[w], d0, d1);
                        g3[n] = f2fma(f0[0], d0, g3[n]); g4[n] = f2fma(f0[1], d0, g4[n]);
                        g5r[1 + n] = f2fma(w5[0], d0, g5r[1 + n]);
                        g3[n] = f2fma(f1[0], d1, g3[n]); g4[n] = f2fma(f1[1], d1, g4[n]);
                        g5r[1 + n] = f2fma(w5[1], d1, g5r[1 + n]);
                    }
                }
            }
#pragma unroll
            for (int n = 0; n < 5; n++) {
                ULL s3 = f2add(g3[n], u3r[1 + n]), s4 = f2add(g4[n], u3r[1 + n]);
                float s3x, s3y, s4x, s4y, ox, oy;
                upk(s3, s3x, s3y); upk(s4, s4x, s4y);
                upk(nodes2p[(it0 + n) * RSU + h2], ox, oy);
                *reinterpret_cast<uint32_t*>(mh16 + (it0 + n) * NBROW + h2 * 4) =
                    f2h2(sigm(s4x) * ox, sigm(s4y) * oy);
                a2p[(it0 + n) * RSU + h2] = pk2(sigm(s3x), sigm(s3y));
            }
        }
        __syncthreads();

        // ---- B2: hv = tanh(g5 + m(fp16) @ W5u^T + b5u); node update ----
        {
            ULL acc[6];
            const ULL b5u2 = *reinterpret_cast<const ULL*>(sm + OFF_B5U + 2 * h2);
#pragma unroll
            for (int n = 0; n < 6; n++) acc[n] = b5u2;
#pragma unroll
            for (int q2 = 0; q2 < 4; q2++) {
                uint4 m4[6];
#pragma unroll
                for (int n = 0; n < 6; n++)
                    m4[n] = *reinterpret_cast<const uint4*>(mh16 + ii[n] * NBROW + q2 * 16);
#pragma unroll
                for (int w = 0; w < 4; w++) {
                    int k2 = q2 * 4 + w;
                    float4 wp = *reinterpret_cast<const float4*>(sm + OFF_W5U + (k2 * 16 + h2) * 4);
                    const ULL* wu = reinterpret_cast<const ULL*>(&wp);
#pragma unroll
                    for (int n = 0; n < 6; n++) {
                        ULL d0, d1; h2dup(reinterpret_cast<const uint32_t*>(&m4[n])[w], d0, d1);
                        acc[n] = f2fma(wu[0], d0, acc[n]);
                        acc[n] = f2fma(wu[1], d1, acc[n]);
                    }
                }
            }
#pragma unroll
            for (int n = 0; n < 6; n++) {
                ULL hpre = f2add(g5r[n], acc[n]);
                float hx, hy, ox, oy, zx, zy;
                upk(hpre, hx, hy);
                upk(nodes2p[ii[n] * RSU + h2], ox, oy);
                upk(a2p[ii[n] * RSU + h2], zx, zy);
                hx = tanhf_(hx); hy = tanhf_(hy);
                float nx = fmaf(zx, hx - ox, ox), ny = fmaf(zy, hy - oy, oy);
                nodes2p[ii[n] * RSU + h2] = pk2(nx, ny);
                *reinterpret_cast<uint32_t*>(nh16 + ii[n] * NBROW + h2 * 4) = f2h2(nx, ny);
            }
        }
        __syncthreads();
    }

    // ================= readout =================
    // F0: out = tanh(nodes@WoT_lo + XC + bo) -> AP
#pragma unroll 1
    for (int q = 0; q < 6; q++) {
        int item = t + (q << 8);
        int i = item >> 4, o = item & 15;
        const float* nrow = sm + OFF_NODESP + i * RS;
        float acc0 = sm[OFF_BO + o] + sm[OFF_XC + i * 16 + o];
#pragma unroll
        for (int k = 0; k < 32; k++)
            acc0 = fmaf(sm[OFF_WOT + k * 16 + o], nrow[k], acc0);
        sm[OFF_AP + i * 16 + o] = tanhf_(acc0);
    }
    // F1: rfcx (MP, stride 16) / rfcy (MP+256, stride 17)
    {
        int i = t >> 4, o = t & 15;
        const float* nrow = sm + OFF_NODESP + i * RS;
        float acc = sm[OFF_BRX + o];
#pragma unroll
        for (int k = 0; k < 32; k++) acc = fmaf(sm[OFF_WRXT + k * 16 + o], nrow[k], acc);
        sm[OFF_MP + i * 16 + o] = tanhf_(acc);
    }
#pragma unroll 1
    for (int q = 1; q < 6; q++) {
        int item = t + (q << 8);
        int j = (item - 256) >> 4, o = item & 15;
        const float* nrow = sm + OFF_NODESP + (16 + j) * RS;
        float acc = sm[OFF_BRY + o];
#pragma unroll
        for (int k = 0; k < 32; k++) acc = fmaf(sm[OFF_WRYT + k * 16 + o], nrow[k], acc);
        sm[OFF_MP + 256 + j * 17 + o] = tanhf_(acc);
    }
    __syncthreads();

    // F2: s = sigmoid(sum Wr2*rfcx*rfcy + br2) * mask
#pragma unroll 1
    for (int q = 0; q < 5; q++) {
        int item = t + (q << 8);
        int i = item / 80;
        int j = item - i * 80;
        const float* rx = sm + OFF_MP + i * 16;
        const float* ry = sm + OFF_MP + 256 + j * 17;
        float acc = sm[OFF_BR2];
#pragma unroll
        for (int o = 0; o < 16; o++) acc = fmaf(sm[OFF_WR2 + o] * rx[o], ry[o], acc);
        uint32_t mb = reinterpret_cast<uint32_t*>(sm + OFF_MB)[i * 3 + (j >> 5)];
        float msk = (float)((mb >> (j & 31)) & 1u);
        sm[OFF_MP + 1616 + item] = sigm(acc) * msk;
    }
    __syncthreads();

    // Final write
    {
        float4* og = reinterpret_cast<float4*>(outp) + (size_t)b * 5184;
#pragma unroll 1
        for (int q = 0; q < 21; q++) {
            int idx = t + (q << 8);
            if (idx < 5184) {
                int i = idx / 324;
                int rem = idx - i * 324;
                int k = rem >> 2, o4 = rem & 3;
                float4 v;
                if (k == 0) {
                    v = *reinterpret_cast<const float4*>(sm + OFF_AP + i * 16 + o4 * 4);
                } else {
                    int j = k - 1;
                    float sv = sm[OFF_MP + 1616 + i * 80 + j];
                    float4 u = *reinterpret_cast<const float4*>(sm + OFF_AP + (16 + j) * 16 + o4 * 4);
                    v = make_float4(u.x * sv, u.y * sv, u.z * sv, u.w * sv);
                }
                og[idx] = v;
            }
        }
    }
}

extern "C" void kernel_launch(void* const* d_in, const int* in_sizes, int n_in,
                              void* d_out, int out_size) {
    (void)in_sizes; (void)n_in; (void)out_size;
    cudaFuncSetAttribute(ggnn_kernel, cudaFuncAttributeMaxDynamicSharedMemorySize, SMEM_BYTES);
    ggnn_kernel<<<4096, 256, SMEM_BYTES>>>(
        (const float*)d_in[0],              // input
        (const float*)d_in[3],              // mask
        (const float*)d_in[4],  (const float*)d_in[5],   // W3w, b3w
        (const float*)d_in[6],  (const float*)d_in[7],   // W3u, b3u
        (const float*)d_in[8],  (const float*)d_in[9],   // W4w, b4w
        (const float*)d_in[10], (const float*)d_in[11],  // W5w, b5w
        (const float*)d_in[12], (const float*)d_in[13],  // W5u, b5u
        (const float*)d_in[14], (const float*)d_in[15],  // Wo, bo
        (const float*)d_in[16], (const float*)d_in[17],  // Wrx, brx
        (const float*)d_in[18], (const float*)d_in[19],  // Wry, bry
        (const float*)d_in[20], (const float*)d_in[21],  // Wr2, br2
        (float*)d_out);
}

// round 14
// speedup vs baseline: 1.0004x; 1.0004x over previous
#include <cuda_runtime.h>
#include <cstdint>
#include <cstddef>

#define ULL unsigned long long

__device__ __forceinline__ ULL pks(float s) {
    ULL r; asm("mov.b64 %0, {%1, %1};" : "=l"(r) : "f"(s)); return r;
}
__device__ __forceinline__ ULL pk2(float lo, float hi) {
    ULL r; asm("mov.b64 %0, {%1, %2};" : "=l"(r) : "f"(lo), "f"(hi)); return r;
}
__device__ __forceinline__ void upk(ULL v, float& lo, float& hi) {
    asm("mov.b64 {%0, %1}, %2;" : "=f"(lo), "=f"(hi) : "l"(v));
}
__device__ __forceinline__ ULL f2fma(ULL a, ULL b, ULL c) {
    ULL d; asm("fma.rn.f32x2 %0, %1, %2, %3;" : "=l"(d) : "l"(a), "l"(b), "l"(c)); return d;
}
__device__ __forceinline__ ULL f2add(ULL a, ULL b) {
    ULL d; asm("add.rn.f32x2 %0, %1, %2;" : "=l"(d) : "l"(a), "l"(b)); return d;
}
// fp16x2 word -> packed f32x2 (lo -> lo)
__device__ __forceinline__ ULL h2f2(uint32_t w) {
    float lo, hi;
    asm("{\n\t.reg .f16 l, h;\n\tmov.b32 {l, h}, %2;\n\tcvt.f32.f16 %0, l;\n\tcvt.f32.f16 %1, h;\n\t}"
        : "=f"(lo), "=f"(hi) : "r"(w));
    return pk2(lo, hi);
}
// fp16x2 word -> two duplicated packed f32x2 operands
__device__ __forceinline__ void h2dup(uint32_t w, ULL& d0, ULL& d1) {
    float lo, hi;
    asm("{\n\t.reg .f16 l, h;\n\tmov.b32 {l, h}, %2;\n\tcvt.f32.f16 %0, l;\n\tcvt.f32.f16 %1, h;\n\t}"
        : "=f"(lo), "=f"(hi) : "r"(w));
    d0 = pks(lo); d1 = pks(hi);
}
__device__ __forceinline__ uint32_t f2h2(float lo, float hi) {
    uint32_t r; asm("cvt.rn.f16x2.f32 %0, %1, %2;" : "=r"(r) : "f"(hi), "f"(lo)); return r;
}
__device__ __forceinline__ float sigm(float x) { return __fdividef(1.f, 1.f + __expf(-x)); }
__device__ __forceinline__ float tanhf_(float x) {
    float ax = fabsf(x);
    float e = __expf(-2.f * ax);
    return copysignf(__fdividef(1.f - e, 1.f + e), x);
}

// ---- shared memory layout (float offsets) ----
#define OFF_W3U  0       // k-pair packed, 1024
#define OFF_W5U  1024    // 1024
#define OFF_W34A 2048    // [k][h2][w3lo,w3hi,w4lo,w4hi] 2048
#define OFF_W34B 4096    // 2048
#define OFF_W5A  6144    // k-pair packed 1024
#define OFF_W5B  7168    // 1024
#define OFF_WOT  8192    // 1024
#define OFF_WRXT 9216    // 512
#define OFF_WRYT 9728    // 512
#define OFF_WR2  10240   // 16
#define OFF_B3W  10256
#define OFF_B3U  10288
#define OFF_B4W  10320
#define OFF_B5W  10352
#define OFF_B5U  10384
#define OFF_BO   10416
#define OFF_BRX  10432
#define OFF_BRY  10448
#define OFF_BR2  10464   // 16
#define OFF_MB   10480   // mask bitset u32[48]
#define OFF_XC   10528   // precomputed x0 @ WoT_hi: 96x16 = 1536
#define OFF_NODESP 12064 // fp32 nodes 97 x 36 (row 96 = zero)
#define OFF_AP   15556   // 3456: z parking (loop) / out[96][16] (readout)
#define OFF_MP   19012   // 2100: readout scratch (rfcx 256, rfcy 1360, s 400)
#define OFF_NH16 21112   // fp16 nodes: 97 x 80B = 1940
#define OFF_AH16 23052   // fp16 a: 96 x 80B = 1920
#define OFF_MH16 24972   // fp16 m: 96 x 80B = 1920
#define OFF_HL   26892   // u16 headlist[16][80] = 640
#define OFF_TL   27532   // u16 taillist[80][16] = 640
#define OFF_HC   28172   // int[16]
#define OFF_TC   28188   // int[80]
#define SMEM_FLOATS 28268
#define SMEM_BYTES (SMEM_FLOATS * 4)   // 113,072 B -> 2 CTAs/SM

#define RS 36
#define RSU 18
#define NBROW 80   // fp16 row stride in bytes

__global__ void __launch_bounds__(256, 2)
ggnn_kernel(const float* __restrict__ xin,
            const float* __restrict__ maskg,
            const float* __restrict__ W3w, const float* __restrict__ b3w,
            const float* __restrict__ W3u, const float* __restrict__ b3u,
            const float* __restrict__ W4w, const float* __restrict__ b4w,
            const float* __restrict__ W5w, const float* __restrict__ b5w,
            const float* __restrict__ W5u, const float* __restrict__ b5u,
            const float* __restrict__ Wo,  const float* __restrict__ bo,
            const float* __restrict__ Wrx, const float* __restrict__ brx,
            const float* __restrict__ Wry, const float* __restrict__ bry,
            const float* __restrict__ Wr2, const float* __restrict__ br2,
            float* __restrict__ outp)
{
    extern __shared__ float sm[];
    const int t = threadIdx.x;
    const int b = blockIdx.x;
    char* nh16 = reinterpret_cast<char*>(sm + OFF_NH16);
    char* ah16 = reinterpret_cast<char*>(sm + OFF_AH16);
    char* mh16 = reinterpret_cast<char*>(sm + OFF_MH16);

    // ---- stage weights + biases + nodes ----
    for (int idx = t; idx < 2048; idx += 256) {
        int quad = idx >> 2, q = idx & 3;
        int k = quad >> 4, h2i = quad & 15;
        int h = 2 * h2i + (q & 1);
        const float* Wsrc = (q < 2) ? W3w : W4w;
        sm[OFF_W34A + idx] = Wsrc[h * 64 + k];
        sm[OFF_W34B + idx] = Wsrc[h * 64 + 32 + k];
    }
    for (int idx = t; idx < 1024; idx += 256) {
        int j = idx & 3, h2i = (idx >> 2) & 15, k2 = idx >> 6;
        int k = 2 * k2 + (j >> 1), h = 2 * h2i + (j & 1);
        sm[OFF_W3U + idx] = W3u[h * 32 + k];
        sm[OFF_W5U + idx] = W5u[h * 32 + k];
        sm[OFF_W5A + idx] = W5w[h * 64 + k];
        sm[OFF_W5B + idx] = W5w[h * 64 + 32 + k];
        int k2o = idx >> 4, o = idx & 15;
        sm[OFF_WOT + idx] = Wo[o * 64 + k2o];
    }
    for (int idx = t; idx < 512; idx += 256) {
        int k = idx >> 4, o = idx & 15;
        sm[OFF_WRXT + idx] = Wrx[o * 32 + k];
        sm[OFF_WRYT + idx] = Wry[o * 32 + k];
    }
    if (t < 32) {
        sm[OFF_B3W + t] = b3w[t]; sm[OFF_B3U + t] = b3u[t];
        sm[OFF_B4W + t] = b4w[t]; sm[OFF_B5W + t] = b5w[t];
        sm[OFF_B5U + t] = b5u[t];
    }
    if (t < 16) {
        sm[OFF_BO + t] = bo[t]; sm[OFF_BRX + t] = brx[t];
        sm[OFF_BRY + t] = bry[t]; sm[OFF_WR2 + t] = Wr2[t];
    }
    if (t == 0) sm[OFF_BR2] = br2[0];
    if (t < 36) sm[OFF_NODESP + 96 * RS + t] = 0.f;
    if (t < 20) reinterpret_cast<uint32_t*>(nh16 + 96 * NBROW)[t] = 0u;
    {
        const float4* xp = reinterpret_cast<const float4*>(xin + (size_t)b * 3072);
#pragma unroll
        for (int q = 0; q < 3; q++) {
            int idx = t + (q << 8);
            float4 v = xp[idx];
            int i = idx >> 3, kq = idx & 7;
            *reinterpret_cast<float4*>(sm + OFF_NODESP + i * RS + kq * 4) = v;
            uint32_t lo = f2h2(v.x, v.y), hi = f2h2(v.z, v.w);
            *reinterpret_cast<ULL*>(nh16 + i * NBROW + kq * 8) = ((ULL)hi << 32) | lo;
        }
    }
    __syncthreads();

    // ---- XC = x0 @ WoT_hi (static part of readout) + sparse lists + bitset ----
#pragma unroll 1
    for (int q = 0; q < 6; q++) {
        int item = t + (q << 8);
        int i = item >> 4, o = item & 15;
        const float* nrow = sm + OFF_NODESP + i * RS;   // == x0 now
        float acc = 0.f;
#pragma unroll
        for (int k = 0; k < 32; k++) acc = fmaf(sm[OFF_WOT + (32 + k) * 16 + o], nrow[k], acc);
        sm[OFF_XC + i * 16 + o] = acc;
    }
    uint16_t* hl16 = reinterpret_cast<uint16_t*>(sm + OFF_HL);
    uint16_t* tl16 = reinterpret_cast<uint16_t*>(sm + OFF_TL);
    int* headcnt = reinterpret_cast<int*>(sm + OFF_HC);
    int* tailcnt = reinterpret_cast<int*>(sm + OFF_TC);
    uint32_t* mbits = reinterpret_cast<uint32_t*>(sm + OFF_MB);
    if (t < 16) {
        int c = 0;
        uint32_t w0 = 0, w1 = 0, w2 = 0;
        for (int j = 0; j < 80; j++) {
            if (maskg[t * 80 + j] != 0.f) {
                hl16[t * 80 + c++] = (uint16_t)((16 + j) * NBROW);
                if (j < 32) w0 |= 1u << j;
                else if (j < 64) w1 |= 1u << (j - 32);
                else w2 |= 1u << (j - 64);
            }
        }
        if (c & 1) hl16[t * 80 + c++] = (uint16_t)(96 * NBROW);
        headcnt[t] = c;
        mbits[t * 3 + 0] = w0; mbits[t * 3 + 1] = w1; mbits[t * 3 + 2] = w2;
    } else if (t < 96) {
        int j = t - 16, c = 0;
        for (int i = 0; i < 16; i++)
            if (maskg[i * 80 + j] != 0.f) tl16[j * 16 + c++] = (uint16_t)(i * NBROW);
        if (c & 1) tl16[j * 16 + c++] = (uint16_t)(96 * NBROW);
        tailcnt[j] = c;
    }
    __syncthreads();

    const int h2 = t & 15;
    const int g  = t >> 4;
    const int it0 = 16 + g * 5;
    const int ii[6] = { g, it0, it0 + 1, it0 + 2, it0 + 3, it0 + 4 };

    ULL* nodes2p = reinterpret_cast<ULL*>(sm + OFF_NODESP);
    ULL* a2p     = reinterpret_cast<ULL*>(sm + OFF_AP);   // z parking

    // ================= T=5 recurrent iterations =================
#pragma unroll 1
    for (int step = 0; step < 5; step++) {
        // ---- Phase A: sparse message pass (fp16 in, fp16 out) ----
#pragma unroll 1
        for (int c = 0; c < 3; c++) {
            int item = t + (c << 8);
            int r = item >> 3, q = item & 7;
            int cnt;
            const uint16_t* lst;
            if (r < 16) { cnt = headcnt[r]; lst = hl16 + r * 80; }
            else        { cnt = tailcnt[r - 16]; lst = tl16 + (r - 16) * 16; }
            const char* nbq = nh16 + q * 8;
            ULL acc0 = 0, acc1 = 0;
            for (int ci = 0; ci < cnt; ci += 2) {
                uint32_t wv = *reinterpret_cast<const uint32_t*>(lst + ci);
                ULL p0 = *reinterpret_cast<const ULL*>(nbq + (wv & 0xFFFF));
                ULL p1 = *reinterpret_cast<const ULL*>(nbq + (wv >> 16));
                acc0 = f2add(acc0, h2f2((uint32_t)p0));
                acc1 = f2add(acc1, h2f2((uint32_t)(p0 >> 32)));
                acc0 = f2add(acc0, h2f2((uint32_t)p1));
                acc1 = f2add(acc1, h2f2((uint32_t)(p1 >> 32)));
            }
            float a0, a1, a2, a3;
            upk(acc0, a0, a1); upk(acc1, a2, a3);
            uint32_t lo = f2h2(a0, a1), hi = f2h2(a2, a3);
            *reinterpret_cast<ULL*>(ah16 + r * NBROW + q * 8) = ((ULL)hi << 32) | lo;
        }
        __syncthreads();

        // ---- B1a: u3 = nodes(fp16) @ W3u^T + b3u (NB=6) ----
        ULL u3r[6];
        {
            const ULL b3u2 = *reinterpret_cast<const ULL*>(sm + OFF_B3U + 2 * h2);
#pragma unroll
            for (int n = 0; n < 6; n++) u3r[n] = b3u2;
#pragma unroll
            for (int q2 = 0; q2 < 4; q2++) {
                uint4 n4[6];
#pragma unroll
                for (int n = 0; n < 6; n++)
                    n4[n] = *reinterpret_cast<const uint4*>(nh16 + ii[n] * NBROW + q2 * 16);
#pragma unroll
                for (int w = 0; w < 4; w++) {
                    int k2 = q2 * 4 + w;
                    float4 wp = *reinterpret_cast<const float4*>(sm + OFF_W3U + (k2 * 16 + h2) * 4);
                    const ULL* wu = reinterpret_cast<const ULL*>(&wp);
#pragma unroll
                    for (int n = 0; n < 6; n++) {
                        ULL d0, d1; h2dup(reinterpret_cast<const uint32_t*>(&n4[n])[w], d0, d1);
                        u3r[n] = f2fma(wu[0], d0, u3r[n]);
                        u3r[n] = f2fma(wu[1], d1, u3r[n]);
                    }
                }
            }
        }

        ULL g5r[6];
        // ---- B1b: head gates (NB=1, a-weight set) ----
        {
            ULL g3 = *reinterpret_cast<const ULL*>(sm + OFF_B3W + 2 * h2);
            ULL g4 = *reinterpret_cast<const ULL*>(sm + OFF_B4W + 2 * h2);
            ULL g5 = *reinterpret_cast<const ULL*>(sm + OFF_B5W + 2 * h2);
#pragma unroll
            for (int q2 = 0; q2 < 4; q2++) {
                uint4 a4 = *reinterpret_cast<const uint4*>(ah16 + g * NBROW + q2 * 16);
#pragma unroll
                for (int w = 0; w < 4; w++) {
                    int k2 = q2 * 4 + w;
                    float4 wf0 = *reinterpret_cast<const float4*>(sm + OFF_W34A + ((2 * k2) * 16 + h2) * 4);
                    float4 wf1 = *reinterpret_cast<const float4*>(sm + OFF_W34A + ((2 * k2 + 1) * 16 + h2) * 4);
                    float4 w5p = *reinterpret_cast<const float4*>(sm + OFF_W5A + (k2 * 16 + h2) * 4);
                    const ULL* f0 = reinterpret_cast<const ULL*>(&wf0);
                    const ULL* f1 = reinterpret_cast<const ULL*>(&wf1);
                    const ULL* w5 = reinterpret_cast<const ULL*>(&w5p);
                    ULL d0, d1; h2dup(reinterpret_cast<const uint32_t*>(&a4)[w], d0, d1);
                    g3 = f2fma(f0[0], d0, g3); g4 = f2fma(f0[1], d0, g4); g5 = f2fma(w5[0], d0, g5);
                    g3 = f2fma(f1[0], d1, g3); g4 = f2fma(f1[1], d1, g4); g5 = f2fma(w5[1], d1, g5);
                }
            }
            ULL s3 = f2add(g3, u3r[0]), s4 = f2add(g4, u3r[0]);
            float s3x, s3y, s4x, s4y, ox, oy;
            upk(s3, s3x, s3y); upk(s4, s4x, s4y);
            upk(nodes2p[g * RSU + h2], ox, oy);
            *reinterpret_cast<uint32_t*>(mh16 + g * NBROW + h2 * 4) = f2h2(sigm(s4x) * ox, sigm(s4y) * oy);
            a2p[g * RSU + h2] = pk2(sigm(s3x), sigm(s3y));   // park z
            g5r[0] = g5;
        }

        // ---- B1c: tail gates (NB=5, b-weight set) ----
        {
            ULL g3[5], g4[5];
            {
                const ULL b3w2 = *reinterpret_cast<const ULL*>(sm + OFF_B3W + 2 * h2);
                const ULL b4w2 = *reinterpret_cast<const ULL*>(sm + OFF_B4W + 2 * h2);
                const ULL b5w2 = *reinterpret_cast<const ULL*>(sm + OFF_B5W + 2 * h2);
#pragma unroll
                for (int n = 0; n < 5; n++) { g3[n] = b3w2; g4[n] = b4w2; g5r[1 + n] = b5w2; }
            }
#pragma unroll
            for (int q2 = 0; q2 < 4; q2++) {
                uint4 a4[5];
#pragma unroll
                for (int n = 0; n < 5; n++)
                    a4[n] = *reinterpret_cast<const uint4*>(ah16 + (it0 + n) * NBROW + q2 * 16);
#pragma unroll
                for (int w = 0; w < 4; w++) {
                    int k2 = q2 * 4 + w;
                    float4 wf0 = *reinterpret_cast<const float4*>(sm + OFF_W34B + ((2 * k2) * 16 + h2) * 4);
                    float4 wf1 = *reinterpret_cast<const float4*>(sm + OFF_W34B + ((2 * k2 + 1) * 16 + h2) * 4);
                    float4 w5p = *reinterpret_cast<const float4*>(sm + OFF_W5B + (k2 * 16 + h2) * 4);
                    const ULL* f0 = reinterpret_cast<const ULL*>(&wf0);
                    const ULL* f1 = reinterpret_cast<const ULL*>(&wf1);
                    const ULL* w5 = reinterpret_cast<const ULL*>(&w5p);
#pragma unroll
                    for (int n = 0; n < 5; n++) {
                        ULL d0, d1; h2dup(reinterpret_cast<const uint32_t*>(&a4[n])[w], d0, d1);
                        g3[n] = f2fma(f0[0], d0, g3[n]); g4[n] = f2fma(f0[1], d0, g4[n]);
                        g5r[1 + n] = f2fma(w5[0], d0, g5r[1 + n]);
                        g3[n] = f2fma(f1[0], d1, g3[n]); g4[n] = f2fma(f1[1], d1, g4[n]);
                        g5r[1 + n] = f2fma(w5[1], d1, g5r[1 + n]);
                    }
                }
            }
#pragma unroll
            for (int n = 0; n < 5; n++) {
                ULL s3 = f2add(g3[n], u3r[1 + n]), s4 = f2add(g4[n], u3r[1 + n]);
                float s3x, s3y, s4x, s4y, ox, oy;
                upk(s3, s3x, s3y); upk(s4, s4x, s4y);
                upk(nodes2p[(it0 + n) * RSU + h2], ox, oy);
                *reinterpret_cast<uint32_t*>(mh16 + (it0 + n) * NBROW + h2 * 4) =
                    f2h2(sigm(s4x) * ox, sigm(s4y) * oy);
                a2p[(it0 + n) * RSU + h2] = pk2(sigm(s3x), sigm(s3y));
            }
        }
        __syncthreads();

        // ---- B2: hv = tanh(g5 + m(fp16) @ W5u^T + b5u); node update ----
        {
            ULL acc[6];
            const ULL b5u2 = *reinterpret_cast<const ULL*>(sm + OFF_B5U + 2 * h2);
#pragma unroll
            for (int n = 0; n < 6; n++) acc[n] = b5u2;
#pragma unroll
            for (int q2 = 0; q2 < 4; q2++) {
                uint4 m4[6];
#pragma unroll
                for (int n = 0; n < 6; n++)
                    m4[n] = *reinterpret_cast<const uint4*>(mh16 + ii[n] * NBROW + q2 * 16);
#pragma unroll
                for (int w = 0; w < 4; w++) {
                    int k2 = q2 * 4 + w;
                    float4 wp = *reinterpret_cast<const float4*>(sm + OFF_W5U + (k2 * 16 + h2) * 4);
                    const ULL* wu = reinterpret_cast<const ULL*>(&wp);
#pragma unroll
                    for (int n = 0; n < 6; n++) {
                        ULL d0, d1; h2dup(reinterpret_cast<const uint32_t*>(&m4[n])[w], d0, d1);
                        acc[n] = f2fma(wu[0], d0, acc[n]);
                        acc[n] = f2fma(wu[1], d1, acc[n]);
                    }
                }
            }
#pragma unroll
            for (int n = 0; n < 6; n++) {
                ULL hpre = f2add(g5r[n], acc[n]);
                float hx, hy, ox, oy, zx, zy;
                upk(hpre, hx, hy);
                upk(nodes2p[ii[n] * RSU + h2], ox, oy);
                upk(a2p[ii[n] * RSU + h2], zx, zy);
                hx = tanhf_(hx); hy = tanhf_(hy);
                float nx = fmaf(zx, hx - ox, ox), ny = fmaf(zy, hy - oy, oy);
                nodes2p[ii[n] * RSU + h2] = pk2(nx, ny);
                *reinterpret_cast<uint32_t*>(nh16 + ii[n] * NBROW + h2 * 4) = f2h2(nx, ny);
            }
        }
        __syncthreads();
    }

    // ================= readout =================
    // F0: out = tanh(nodes@WoT_lo + XC + bo) -> AP
#pragma unroll 1
    for (int q = 0; q < 6; q++) {
        int item = t + (q << 8);
        int i = item >> 4, o = item & 15;
        const float* nrow = sm + OFF_NODESP + i * RS;
        float acc0 = sm[OFF_BO + o] + sm[OFF_XC + i * 16 + o];
#pragma unroll
        for (int k = 0; k < 32; k++)
            acc0 = fmaf(sm[OFF_WOT + k * 16 + o], nrow[k], acc0);
        sm[OFF_AP + i * 16 + o] = tanhf_(acc0);
    }
    // F1: rfcx (MP, stride 16) / rfcy (MP+256, stride 17)
    {
        int i = t >> 4, o = t & 15;
        const float* nrow = sm + OFF_NODESP + i * RS;
        float acc = sm[OFF_BRX + o];
#pragma unroll
        for (int k = 0; k < 32; k++) acc = fmaf(sm[OFF_WRXT + k * 16 + o], nrow[k], acc);
        sm[OFF_MP + i * 16 + o] = tanhf_(acc);
    }
#pragma unroll 1
    for (int q = 1; q < 6; q++) {
        int item = t + (q << 8);
        int j = (item - 256) >> 4, o = item & 15;
        const float* nrow = sm + OFF_NODESP + (16 + j) * RS;
        float acc = sm[OFF_BRY + o];
#pragma unroll
        for (int k = 0; k < 32; k++) acc = fmaf(sm[OFF_WRYT + k * 16 + o], nrow[k], acc);
        sm[OFF_MP + 256 + j * 17 + o] = tanhf_(acc);
    }
    __syncthreads();

    // F2: s = sigmoid(sum Wr2*rfcx*rfcy + br2) * mask
#pragma unroll 1
    for (int q = 0; q < 5; q++) {
        int item = t + (q << 8);
        int i = item / 80;
        int j = item - i * 80;
        const float* rx = sm + OFF_MP + i * 16;
        const float* ry = sm + OFF_MP + 256 + j * 17;
        float acc = sm[OFF_BR2];
#pragma unroll
        for (int o = 0; o < 16; o++) acc = fmaf(sm[OFF_WR2 + o] * rx[o], ry[o], acc);
        uint32_t mb = reinterpret_cast<uint32_t*>(sm + OFF_MB)[i * 3 + (j >> 5)];
        float msk = (float)((mb >> (j & 31)) & 1u);
        sm[OFF_MP + 1616 + item] = sigm(acc) * msk;
    }
    __syncthreads();

    // Final write
    {
        float4* og = reinterpret_cast<float4*>(outp) + (size_t)b * 5184;
#pragma unroll 1
        for (int q = 0; q < 21; q++) {
            int idx = t + (q << 8);
            if (idx < 5184) {
                int i = idx / 324;
                int rem = idx - i * 324;
                int k = rem >> 2, o4 = rem & 3;
                float4 v;
                if (k == 0) {
                    v = *reinterpret_cast<const float4*>(sm + OFF_AP + i * 16 + o4 * 4);
                } else {
                    int j = k - 1;
                    float sv = sm[OFF_MP + 1616 + i * 80 + j];
                    float4 u = *reinterpret_cast<const float4*>(sm + OFF_AP + (16 + j) * 16 + o4 * 4);
                    v = make_float4(u.x * sv, u.y * sv, u.z * sv, u.w * sv);
                }
                og[idx] = v;
            }
        }
    }
}

extern "C" void kernel_launch(void* const* d_in, const int* in_sizes, int n_in,
                              void* d_out, int out_size) {
    (void)in_sizes; (void)n_in; (void)out_size;
    cudaFuncSetAttribute(ggnn_kernel, cudaFuncAttributeMaxDynamicSharedMemorySize, SMEM_BYTES);
    ggnn_kernel<<<4096, 256, SMEM_BYTES>>>(
        (const float*)d_in[0],              // input
        (const float*)d_in[3],              // mask
        (const float*)d_in[4],  (const float*)d_in[5],   // W3w, b3w
        (const float*)d_in[6],  (const float*)d_in[7],   // W3u, b3u
        (const float*)d_in[8],  (const float*)d_in[9],   // W4w, b4w
        (const float*)d_in[10], (const float*)d_in[11],  // W5w, b5w
        (const float*)d_in[12], (const float*)d_in[13],  // W5u, b5u
        (const float*)d_in[14], (const float*)d_in[15],  // Wo, bo
        (const float*)d_in[16], (const float*)d_in[17],  // Wrx, brx
        (const float*)d_in[18], (const float*)d_in[19],  // Wry, bry
        (const float*)d_in[20], (const float*)d_in[21],  // Wr2, br2
        (float*)d_out);
}

// round 16
// speedup vs baseline: 1.0420x; 1.0415x over previous
#include <cuda_runtime.h>
#include <cstdint>
#include <cstddef>

__device__ __forceinline__ uint32_t smem_u32(const void* p){
    uint32_t a; asm("{ .reg .u64 t; cvta.to.shared.u64 t, %1; cvt.u32.u64 %0, t; }":"=r"(a):"l"(p)); return a;
}
__device__ __forceinline__ uint32_t f2h2(float lo, float hi){
    uint32_t r; asm("cvt.rn.f16x2.f32 %0, %1, %2;":"=r"(r):"f"(hi),"f"(lo)); return r;
}
__device__ __forceinline__ uint16_t f2h1(float v){
    uint16_t r; asm("{ .reg .f16 h; cvt.rn.f16.f32 h,%1; mov.b16 %0,h; }":"=h"(r):"f"(v)); return r;
}
__device__ __forceinline__ void h2ff(uint32_t w, float& lo, float& hi){
    asm("{ .reg .f16 l,h; mov.b32 {l,h}, %2; cvt.f32.f16 %0,l; cvt.f32.f16 %1,h; }":"=f"(lo),"=f"(hi):"r"(w));
}
__device__ __forceinline__ float ex2f(float x){ float y; asm("ex2.approx.f32 %0, %1;":"=f"(y):"f"(x)); return y; }
__device__ __forceinline__ float frcp(float d){
    float y = __uint_as_float(0x7EF311C3u - __float_as_uint(d));
    y = y * (2.f - d * y); y = y * (2.f - d * y); return y;
}
__device__ __forceinline__ float sigm(float x){ float u = ex2f(-1.4426950409f * x); return frcp(1.f + u); }
__device__ __forceinline__ float tanhf_(float x){
    float ax = fabsf(x), u = ex2f(-2.8853900818f * ax);
    return copysignf((1.f - u) * frcp(1.f + u), x);
}
__device__ __forceinline__ void ldm4(uint32_t a, uint32_t* r){
    asm volatile("ldmatrix.sync.aligned.m8n8.x4.shared.b16 {%0,%1,%2,%3}, [%4];"
        :"=r"(r[0]),"=r"(r[1]),"=r"(r[2]),"=r"(r[3]):"r"(a));
}
__device__ __forceinline__ void ldm2(uint32_t a, uint32_t* r){
    asm volatile("ldmatrix.sync.aligned.m8n8.x2.shared.b16 {%0,%1}, [%2];"
        :"=r"(r[0]),"=r"(r[1]):"r"(a));
}
__device__ __forceinline__ void mmaf(float* c, const uint32_t* a, const uint32_t* b){
    asm volatile("mma.sync.aligned.m16n8k16.row.col.f32.f16.f16.f32 "
        "{%0,%1,%2,%3},{%4,%5,%6,%7},{%8,%9},{%0,%1,%2,%3};"
        :"+f"(c[0]),"+f"(c[1]),"+f"(c[2]),"+f"(c[3])
        :"r"(a[0]),"r"(a[1]),"r"(a[2]),"r"(a[3]),"r"(b[0]),"r"(b[1]));
}
#define SWX(byt,row) ((uint32_t)(byt) ^ ((((uint32_t)(row))&7u)<<4))

// ---- byte-region layout ----
#define B_AVN   0        // fp16 97x256B: [av64 | nodes32 | 1 | 0pad], XOR-swizzled rows
#define B_WCAT  24832    // fp16 96x256B: [Wg(64) | W3u(32) | bias | 0]
#define B_W5U   49408    // fp16 32x128B: [W5u(32) | b5u | 0]
#define B_MA    53504    // fp16 96x128B: [m32 | 1 | 0]
#define B_G     65792    // fp16 96x144B: g3(64B) g4(64B); z overwrites g3
#define B_NODES 79616    // fp32 96x144B
#define B_XC    93440    // fp32 96x16
#define B_HL    99584    // u16[16][80] premult row*256
#define B_TL    102144   // u16[80][16]
#define B_HC    104704   // int[16]
#define B_TC    104768   // int[80]
#define B_MB    105088   // u32[48]
#define SMEM_BYTES 105280
// readout overlay (bytes, inside AVN/WCAT/W5U/MA after loop)
#define RO_WOT  0
#define RO_WRXT 4096
#define RO_WRYT 6144
#define RO_BO   8192
#define RO_BRX  8256
#define RO_BRY  8320
#define RO_WR2  8384
#define RO_BR2  8448
#define RO_OUT  8464
#define RO_RFCX 14608
#define RO_RFCY 15632
#define RO_S    21072

__global__ void __launch_bounds__(256, 2)
ggnn_kernel(const float* __restrict__ xin, const float* __restrict__ maskg,
            const float* __restrict__ W3w, const float* __restrict__ b3w,
            const float* __restrict__ W3u, const float* __restrict__ b3u,
            const float* __restrict__ W4w, const float* __restrict__ b4w,
            const float* __restrict__ W5w, const float* __restrict__ b5w,
            const float* __restrict__ W5u, const float* __restrict__ b5u,
            const float* __restrict__ Wo,  const float* __restrict__ bo,
            const float* __restrict__ Wrx, const float* __restrict__ brx,
            const float* __restrict__ Wry, const float* __restrict__ bry,
            const float* __restrict__ Wr2, const float* __restrict__ br2,
            float* __restrict__ outp)
{
    extern __shared__ float smf[];
    char* S = reinterpret_cast<char*>(smf);
    const uint32_t Sb = smem_u32(S);
    const int t = threadIdx.x, b = blockIdx.x, wid = t >> 5, lane = t & 31;

    // zero AVN (incl. zero-row 96) + MA
    uint4 z4 = make_uint4(0,0,0,0);
    for (int i = t; i < 1552; i += 256) reinterpret_cast<uint4*>(S + B_AVN)[i] = z4;
    for (int i = t; i < 768;  i += 256) reinterpret_cast<uint4*>(S + B_MA)[i]  = z4;
    __syncthreads();

    // stage Wcat (n=gate*32+h, k<128)
    for (int e = t; e < 12288; e += 256) {
        int n = e >> 7, k = e & 127, gate = n >> 5, h = n & 31;
        float v = 0.f;
        if (k < 64) v = (gate==0?W3w:(gate==1?W4w:W5w))[h*64+k];
        else if (k < 96) v = (gate<2) ? W3u[h*32+(k-64)] : 0.f;
        else if (k == 96) v = (gate==0) ? b3w[h]+b3u[h] : (gate==1 ? b4w[h]+b3u[h] : b5w[h]);
        *reinterpret_cast<uint16_t*>(S + B_WCAT + n*256 + SWX(k*2, n)) = f2h1(v);
    }
    // stage W5ucat
    for (int e = t; e < 2048; e += 256) {
        int n = e >> 6, k = e & 63;
        float v = (k < 32) ? W5u[n*32+k] : (k==32 ? b5u[n] : 0.f);
        *reinterpret_cast<uint16_t*>(S + B_W5U + n*128 + SWX(k*2, n)) = f2h1(v);
    }
    // bias columns
    if (t < 96) {
        *reinterpret_cast<uint16_t*>(S + B_AVN + t*256 + SWX(192, t)) = 0x3C00;
        *reinterpret_cast<uint16_t*>(S + B_MA  + t*128 + SWX(64, t))  = 0x3C00;
    }
    // x0 -> NODES fp32 + AVN fp16 node half
    for (int c = 0; c < 3; c++) {
        int idx = t + (c << 8);
        float4 v = reinterpret_cast<const float4*>(xin + (size_t)b*3072)[idx];
        int i = idx >> 3, kq = idx & 7;
        *reinterpret_cast<float4*>(S + B_NODES + i*144 + kq*16) = v;
        unsigned long long pk = ((unsigned long long)f2h2(v.z,v.w) << 32) | f2h2(v.x,v.y);
        *reinterpret_cast<unsigned long long*>(S + B_AVN + i*256 + SWX(128 + kq*8, i)) = pk;
    }
    // sparse lists (premult row*256) + mask bitset
    uint16_t* hl = reinterpret_cast<uint16_t*>(S + B_HL);
    uint16_t* tl = reinterpret_cast<uint16_t*>(S + B_TL);
    int* hc = reinterpret_cast<int*>(S + B_HC);
    int* tc = reinterpret_cast<int*>(S + B_TC);
    uint32_t* mbits = reinterpret_cast<uint32_t*>(S + B_MB);
    if (t < 16) {
        int c = 0; uint32_t w0=0,w1=0,w2=0;
        for (int j = 0; j < 80; j++) if (maskg[t*80+j] != 0.f) {
            hl[t*80+c++] = (uint16_t)((16+j)*256);
            if (j<32) w0|=1u<<j; else if (j<64) w1|=1u<<(j-32); else w2|=1u<<(j-64);
        }
        if (c & 1) hl[t*80+c++] = (uint16_t)(96*256);
        hc[t]=c; mbits[t*3]=w0; mbits[t*3+1]=w1; mbits[t*3+2]=w2;
    } else if (t < 96) {
        int j = t-16, c = 0;
        for (int i = 0; i < 16; i++) if (maskg[i*80+j] != 0.f) tl[j*16+c++] = (uint16_t)(i*256);
        if (c & 1) tl[j*16+c++] = (uint16_t)(96*256);
        tc[j]=c;
    }
    __syncthreads();

    // XC = x0 @ WoT_hi (NODES holds x0 now)
    for (int e = 0; e < 6; e++) {
        int item = t + (e << 8);
        int i = item >> 4, o = item & 15;
        const float* nrow = reinterpret_cast<const float*>(S + B_NODES + i*144);
        float acc = 0.f;
#pragma unroll
        for (int k = 0; k < 32; k++) acc = fmaf(Wo[o*64 + 32 + k], nrow[k], acc);
        reinterpret_cast<float*>(S + B_XC)[i*16 + o] = acc;
    }
    __syncthreads();

    const int mt = wid;
    const int ra = mt*16 + (lane & 15);
    const int kh16 = ((lane >> 4) & 1) * 16;
    const int rb0 = lane & 7;
    const int kbh16 = ((lane >> 3) & 1) * 16;
    const int r0 = mt*16 + (lane >> 2);
    float g5acc[4][4];

    // ================= T=5 iterations =================
#pragma unroll 1
    for (int step = 0; step < 5; step++) {
        // ---- Phase A: sparse message pass (fp16), writes av half of AVN ----
#pragma unroll 1
        for (int c = 0; c < 2; c++) {
            int item = t + (c << 8);
            if (item < 384) {
                int r = item >> 2, q = item & 3;
                int cnt; const uint16_t* lst;
                if (r < 16) { cnt = hc[r]; lst = hl + r*80; }
                else        { cnt = tc[r-16]; lst = tl + (r-16)*16; }
                int bq = 128 + q*16;
                float a0=0,a1=0,a2=0,a3=0,a4=0,a5=0,a6=0,a7=0;
                for (int ci = 0; ci < cnt; ci += 2) {
                    uint32_t w = *reinterpret_cast<const uint32_t*>(lst + ci);
                    uint32_t o0 = w & 0xFFFFu, o1 = w >> 16;
                    uint4 v0 = *reinterpret_cast<const uint4*>(S + B_AVN + o0 + SWX(bq, o0 >> 8));
                    uint4 v1 = *reinterpret_cast<const uint4*>(S + B_AVN + o1 + SWX(bq, o1 >> 8));
                    float lo, hi;
                    h2ff(v0.x,lo,hi); a0+=lo; a1+=hi;  h2ff(v0.y,lo,hi); a2+=lo; a3+=hi;
                    h2ff(v0.z,lo,hi); a4+=lo; a5+=hi;  h2ff(v0.w,lo,hi); a6+=lo; a7+=hi;
                    h2ff(v1.x,lo,hi); a0+=lo; a1+=hi;  h2ff(v1.y,lo,hi); a2+=lo; a3+=hi;
                    h2ff(v1.z,lo,hi); a4+=lo; a5+=hi;  h2ff(v1.w,lo,hi); a6+=lo; a7+=hi;
                }
                uint4 w4 = make_uint4(f2h2(a0,a1), f2h2(a2,a3), f2h2(a4,a5), f2h2(a6,a7));
                int half = (r < 16) ? 0 : 64;
                *reinterpret_cast<uint4*>(S + B_AVN + r*256 + SWX(half + q*16, r)) = w4;
            }
        }
        __syncthreads();

        // ---- MMA2 (warps 0-5): G = AVN @ Wcat^T ; nt 0-7 -> g3/g4 to smem, nt 8-11 -> g5 kept in regs
        if (wid < 6) {
            uint32_t af[7][4];
#pragma unroll
            for (int kt = 0; kt < 7; kt++)
                ldm4(Sb + B_AVN + ra*256 + SWX(kt*32 + kh16, ra), af[kt]);
#pragma unroll 1
            for (int nt = 0; nt < 12; nt++) {
                float acc[4] = {0.f,0.f,0.f,0.f};
                int rb = nt*8 + rb0;
#pragma unroll
                for (int kt = 0; kt < 7; kt++) {
                    uint32_t bf[2];
                    ldm2(Sb + B_WCAT + rb*256 + SWX(kt*32 + kbh16, rb), bf);
                    mmaf(acc, af[kt], bf);
                }
                if (nt < 8) {
                    int cb = (nt*8 + (lane&3)*2) * 2;   // byte in 128B g3|g4 region
                    *reinterpret_cast<uint32_t*>(S + B_G + r0*144 + cb)     = f2h2(acc[0], acc[1]);
                    *reinterpret_cast<uint32_t*>(S + B_G + (r0+8)*144 + cb) = f2h2(acc[2], acc[3]);
                } else {
#pragma unroll
                    for (int x = 0; x < 4; x++) g5acc[nt-8][x] = acc[x];
                }
            }
        }
        __syncthreads();

        // ---- Epilogue1 (all threads): z,r ; m = r.*nodes -> MA ; z over g3 ----
#pragma unroll 1
        for (int e = 0; e < 6; e++) {
            int item = t + (e << 8);
            int row = item >> 4, h2 = item & 15;
            uint32_t g3 = *reinterpret_cast<uint32_t*>(S + B_G + row*144 + h2*4);
            uint32_t g4 = *reinterpret_cast<uint32_t*>(S + B_G + row*144 + 64 + h2*4);
            float z0,z1,rr0,rr1; h2ff(g3,z0,z1); h2ff(g4,rr0,rr1);
            z0 = sigm(z0); z1 = sigm(z1); rr0 = sigm(rr0); rr1 = sigm(rr1);
            float2 nd = *reinterpret_cast<float2*>(S + B_NODES + row*144 + h2*8);
            *reinterpret_cast<uint32_t*>(S + B_MA + row*128 + SWX(h2*4, row)) = f2h2(rr0*nd.x, rr1*nd.y);
            *reinterpret_cast<uint32_t*>(S + B_G + row*144 + h2*4) = f2h2(z0, z1);
        }
        __syncthreads();

        // ---- MMA3 (warps 0-5): H = g5acc + MA @ W5ucat^T ; fused tanh+update ----
        if (wid < 6) {
            uint32_t af3[3][4];
#pragma unroll
            for (int kt = 0; kt < 3; kt++)
                ldm4(Sb + B_MA + ra*128 + SWX(kt*32 + kh16, ra), af3[kt]);
#pragma unroll 1
            for (int nt = 0; nt < 4; nt++) {
                float acc[4];
#pragma unroll
                for (int x = 0; x < 4; x++) acc[x] = g5acc[nt][x];
                int rb = nt*8 + rb0;
#pragma unroll
                for (int kt = 0; kt < 3; kt++) {
                    uint32_t bf[2];
                    ldm2(Sb + B_W5U + rb*128 + SWX(kt*32 + kbh16, rb), bf);
                    mmaf(acc, af3[kt], bf);
                }
                int cc = nt*8 + (lane&3)*2;    // h col pair base
                uint32_t zp0 = *reinterpret_cast<uint32_t*>(S + B_G + r0*144 + cc*2);
                uint32_t zp1 = *reinterpret_cast<uint32_t*>(S + B_G + (r0+8)*144 + cc*2);
                float za, zbv, zc, zd; h2ff(zp0, za, zbv); h2ff(zp1, zc, zd);
                float2 n0 = *reinterpret_cast<float2*>(S + B_NODES + r0*144 + cc*4);
                float2 n1 = *reinterpret_cast<float2*>(S + B_NODES + (r0+8)*144 + cc*4);
                float h0 = tanhf_(acc[0]), h1 = tanhf_(acc[1]);
                float h2v = tanhf_(acc[2]), h3 = tanhf_(acc[3]);
                float u0 = fmaf(za, h0 - n0.x, n0.x), u1 = fmaf(zbv, h1 - n0.y, n0.y);
                float u2 = fmaf(zc, h2v - n1.x, n1.x), u3 = fmaf(zd, h3 - n1.y, n1.y);
                *reinterpret_cast<float2*>(S + B_NODES + r0*144 + cc*4)     = make_float2(u0,u1);
                *reinterpret_cast<float2*>(S + B_NODES + (r0+8)*144 + cc*4) = make_float2(u2,u3);
                *reinterpret_cast<uint32_t*>(S + B_AVN + r0*256 + SWX(128 + cc*2, r0))       = f2h2(u0,u1);
                *reinterpret_cast<uint32_t*>(S + B_AVN + (r0+8)*256 + SWX(128 + cc*2, r0+8)) = f2h2(u2,u3);
            }
        }
        __syncthreads();
    }

    // ================= readout =================
    // stage readout weights into overlay (AVN/WCAT regions now dead)
    for (int i = t; i < 1024; i += 256) { int k2=i>>4, o=i&15; reinterpret_cast<float*>(S+RO_WOT)[i] = Wo[o*64+k2]; }
    for (int i = t; i < 512; i += 256) {
        int k=i>>4, o=i&15;
        reinterpret_cast<float*>(S+RO_WRXT)[i] = Wrx[o*32+k];
        reinterpret_cast<float*>(S+RO_WRYT)[i] = Wry[o*32+k];
    }
    if (t < 16) {
        reinterpret_cast<float*>(S+RO_BO)[t] = bo[t];
        reinterpret_cast<float*>(S+RO_BRX)[t] = brx[t];
        reinterpret_cast<float*>(S+RO_BRY)[t] = bry[t];
        reinterpret_cast<float*>(S+RO_WR2)[t] = Wr2[t];
    }
    if (t == 0) reinterpret_cast<float*>(S+RO_BR2)[0] = br2[0];
    __syncthreads();

    // F0: out = tanh(nodes@WoT_lo + XC + bo)
#pragma unroll 1
    for (int q = 0; q < 6; q++) {
        int item = t + (q << 8);
        int i = item >> 4, o = item & 15;
        const float* nrow = reinterpret_cast<const float*>(S + B_NODES + i*144);
        float acc = reinterpret_cast<float*>(S+RO_BO)[o] + reinterpret_cast<float*>(S+B_XC)[i*16+o];
#pragma unroll
        for (int k = 0; k < 32; k++)
            acc = fmaf(reinterpret_cast<float*>(S+RO_WOT)[k*16+o], nrow[k], acc);
        reinterpret_cast<float*>(S+RO_OUT)[i*16+o] = tanhf_(acc);
    }
    // F1: rfcx / rfcy
    {
        int i = t >> 4, o = t & 15;
        const float* nrow = reinterpret_cast<const float*>(S + B_NODES + i*144);
        float acc = reinterpret_cast<float*>(S+RO_BRX)[o];
#pragma unroll
        for (int k = 0; k < 32; k++)
            acc = fmaf(reinterpret_cast<float*>(S+RO_WRXT)[k*16+o], nrow[k], acc);
        reinterpret_cast<float*>(S+RO_RFCX)[i*16+o] = tanhf_(acc);
    }
#pragma unroll 1
    for (int q = 1; q < 6; q++) {
        int item = t + (q << 8);
        int j = (item - 256) >> 4, o = item & 15;
        const float* nrow = reinterpret_cast<const float*>(S + B_NODES + (16+j)*144);
        float acc = reinterpret_cast<float*>(S+RO_BRY)[o];
#pragma unroll
        for (int k = 0; k < 32; k++)
            acc = fmaf(reinterpret_cast<float*>(S+RO_WRYT)[k*16+o], nrow[k], acc);
        reinterpret_cast<float*>(S+RO_RFCY)[j*17+o] = tanhf_(acc);
    }
    __syncthreads();

    // F2: s = sigmoid(sum Wr2*rfcx*rfcy + br2) * mask
#pragma unroll 1
    for (int q = 0; q < 5; q++) {
        int item = t + (q << 8);
        int i = item / 80, j = item - i*80;
        const float* rx = reinterpret_cast<float*>(S+RO_RFCX) + i*16;
        const float* ry = reinterpret_cast<float*>(S+RO_RFCY) + j*17;
        float acc = reinterpret_cast<float*>(S+RO_BR2)[0];
#pragma unroll
        for (int o = 0; o < 16; o++) acc = fmaf(reinterpret_cast<float*>(S+RO_WR2)[o] * rx[o], ry[o], acc);
        uint32_t mbw = mbits[i*3 + (j>>5)];
        reinterpret_cast<float*>(S+RO_S)[item] = sigm(acc) * (float)((mbw >> (j&31)) & 1u);
    }
    __syncthreads();

    // final write
    {
        float4* og = reinterpret_cast<float4*>(outp) + (size_t)b * 5184;
#pragma unroll 1
        for (int q = 0; q < 21; q++) {
            int idx = t + (q << 8);
            if (idx < 5184) {
                int i = idx / 324, rem = idx - i*324;
                int k = rem >> 2, o4 = rem & 3;
                float4 v;
                if (k == 0) {
                    v = *reinterpret_cast<const float4*>(reinterpret_cast<float*>(S+RO_OUT) + i*16 + o4*4);
                } else {
                    int j = k - 1;
                    float sv = reinterpret_cast<float*>(S+RO_S)[i*80 + j];
                    float4 u = *reinterpret_cast<const float4*>(reinterpret_cast<float*>(S+RO_OUT) + (16+j)*16 + o4*4);
                    v = make_float4(u.x*sv, u.y*sv, u.z*sv, u.w*sv);
                }
                og[idx] = v;
            }
        }
    }
}

extern "C" void kernel_launch(void* const* d_in, const int* in_sizes, int n_in,
                              void* d_out, int out_size) {
    (void)in_sizes; (void)n_in; (void)out_size;
    cudaFuncSetAttribute(ggnn_kernel, cudaFuncAttributeMaxDynamicSharedMemorySize, SMEM_BYTES);
    ggnn_kernel<<<4096, 256, SMEM_BYTES>>>(
        (const float*)d_in[0],  (const float*)d_in[3],
        (const float*)d_in[4],  (const float*)d_in[5],
        (const float*)d_in[6],  (const float*)d_in[7],
        (const float*)d_in[8],  (const float*)d_in[9],
        (const float*)d_in[10], (const float*)d_in[11],
        (const float*)d_in[12], (const float*)d_in[13],
        (const float*)d_in[14], (const float*)d_in[15],
        (const float*)d_in[16], (const float*)d_in[17],
        (const float*)d_in[18], (const float*)d_in[19],
        (const float*)d_in[20], (const float*)d_in[21],
        (float*)d_out);
}